// round 2
// baseline (speedup 1.0000x reference)
#include <cuda_runtime.h>
#include <math.h>

#define BB 512      // batch
#define TT 256      // time steps
#define DIN 400     // input dim
#define HH 128      // hidden
#define G4 512      // 4*H

// ---- scratch (device globals: allocation-free per harness rules) ----
__device__ float g_xg[(size_t)BB * TT * G4];   // [B, T, 4H] precomputed input gates (+bias)  ~268MB
__device__ float g_WihT[DIN * G4];             // Wih^T  [K=400][N=512]
__device__ float g_WhhT[HH * G4];              // Whh^T  [K=128][N=512]
__device__ float g_bias[G4];                   // bih + bhh
__device__ float g_hfinal[BB * HH];            // last hidden state

// ============================================================
// K0: prep — transpose weights, combine biases (tiny, one-shot)
// ============================================================
__global__ void prep_kernel(const float* __restrict__ Wih,
                            const float* __restrict__ Whh,
                            const float* __restrict__ bih,
                            const float* __restrict__ bhh) {
    int i = blockIdx.x * blockDim.x + threadIdx.x;
    int stride = gridDim.x * blockDim.x;
    for (int idx = i; idx < DIN * G4; idx += stride) {
        int k = idx / G4, n = idx % G4;
        g_WihT[idx] = Wih[n * DIN + k];
    }
    for (int idx = i; idx < HH * G4; idx += stride) {
        int k = idx / G4, n = idx % G4;
        g_WhhT[idx] = Whh[n * HH + k];
    }
    if (i < G4) g_bias[i] = bih[i] + bhh[i];
}

// ============================================================
// K1: xg = x[M=131072, K=400] @ WihT[K=400, N=512] + bias
// Classic 128x128x8 register-tiled SGEMM, 256 threads, 8x8/thread
// ============================================================
__global__ __launch_bounds__(256)
void gemm_xg_kernel(const float* __restrict__ x) {
    constexpr int BM = 128, BN = 128, BK = 8;
    __shared__ float As[BK][BM];   // transposed A tile
    __shared__ float Bs[BK][BN];

    const int bn = blockIdx.x;     // 0..3
    const int bm = blockIdx.y;     // 0..1023
    const int tid = threadIdx.x;
    const int tx = tid % 16;       // 16 x 16 thread grid
    const int ty = tid / 16;

    const float* A = x + (size_t)bm * BM * DIN;
    const float* Bm = g_WihT + bn * BN;

    // A tile load map: 128 rows x 8 cols, float4 per thread
    const int arow = tid >> 1;
    const int acol = (tid & 1) * 4;
    // B tile load map: 8 rows x 128 cols, float4 per thread
    const int brow = tid >> 5;
    const int bcol = (tid & 31) * 4;

    float acc[8][8];
    #pragma unroll
    for (int i = 0; i < 8; i++)
        #pragma unroll
        for (int j = 0; j < 8; j++) acc[i][j] = 0.f;

    for (int k0 = 0; k0 < DIN; k0 += BK) {   // 50 iterations (400 % 8 == 0)
        float4 av = *(const float4*)(A + (size_t)arow * DIN + k0 + acol);
        As[acol + 0][arow] = av.x;
        As[acol + 1][arow] = av.y;
        As[acol + 2][arow] = av.z;
        As[acol + 3][arow] = av.w;
        float4 bv = *(const float4*)(Bm + (size_t)(k0 + brow) * G4 + bcol);
        *(float4*)&Bs[brow][bcol] = bv;
        __syncthreads();

        #pragma unroll
        for (int k = 0; k < BK; k++) {
            float am[8], bnv[8];
            #pragma unroll
            for (int i = 0; i < 8; i++) am[i] = As[k][ty * 8 + i];
            #pragma unroll
            for (int j = 0; j < 8; j++) bnv[j] = Bs[k][tx * 8 + j];
            #pragma unroll
            for (int i = 0; i < 8; i++)
                #pragma unroll
                for (int j = 0; j < 8; j++) acc[i][j] += am[i] * bnv[j];
        }
        __syncthreads();
    }

    float* Cp = g_xg + (size_t)bm * BM * G4 + bn * BN;
    #pragma unroll
    for (int i = 0; i < 8; i++) {
        int m = ty * 8 + i;
        #pragma unroll
        for (int j = 0; j < 8; j += 4) {
            int n = tx * 8 + j;
            float4 v;
            v.x = acc[i][j + 0] + g_bias[bn * BN + n + 0];
            v.y = acc[i][j + 1] + g_bias[bn * BN + n + 1];
            v.z = acc[i][j + 2] + g_bias[bn * BN + n + 2];
            v.w = acc[i][j + 3] + g_bias[bn * BN + n + 3];
            *(float4*)(Cp + (size_t)m * G4 + n) = v;
        }
    }
}

// ============================================================
// K2: LSTM scan. 128 CTAs x 256 threads; CTA owns 4 batch rows,
// iterates all T=256 steps locally (batch rows are independent).
// Whh^T streamed from L2 (float2-coalesced), h in smem, c in regs.
// Thread owns ADJACENT gate columns {2*tid, 2*tid+1} so every
// weight load is an LDG.64 (halves LSU issue count vs LDG.32).
// ============================================================
__device__ __forceinline__ float sigmoidf_(float v) {
    return 1.f / (1.f + __expf(-v));
}

__global__ __launch_bounds__(256)
void lstm_kernel() {
    __shared__ float h_s[4][HH];       // 2 KB
    __shared__ float gates_s[4][G4];   // 8 KB

    const int tid = threadIdx.x;
    const int rb = blockIdx.x * 4;     // first batch row of this CTA

    // gate ownership: thread computes adjacent gates {2*tid, 2*tid+1} for all 4 rows
    const int gc = 2 * tid;
    // element ownership for the h/c update: 2 of the 4*128 hidden elems
    const int r0 = tid >> 7, j0 = tid & 127;
    const int r1 = (tid + 256) >> 7, j1 = (tid + 256) & 127;

    // init h = 0, c = 0
    h_s[r0][j0] = 0.f;
    h_s[r1][j1] = 0.f;
    float c0 = 0.f, c1 = 0.f;
    __syncthreads();

    const float* __restrict__ xg_base = g_xg + (size_t)rb * TT * G4;

    for (int t = 0; t < TT; t++) {
        // init accumulators with precomputed input gates (float2 loads)
        const float* xgp = xg_base + (size_t)t * G4 + gc;
        float2 x0 = *(const float2*)(xgp + 0 * TT * G4);
        float2 x1 = *(const float2*)(xgp + 1 * TT * G4);
        float2 x2 = *(const float2*)(xgp + 2 * TT * G4);
        float2 x3 = *(const float2*)(xgp + 3 * TT * G4);
        float a00 = x0.x, a01 = x1.x, a02 = x2.x, a03 = x3.x;  // col gc
        float a10 = x0.y, a11 = x1.y, a12 = x2.y, a13 = x3.y;  // col gc+1

        // gates += h @ Whh^T   (Whh^T float2 from L2, h broadcast from smem)
        #pragma unroll 4
        for (int k = 0; k < HH; k++) {
            float2 w = *(const float2*)(g_WhhT + k * G4 + gc);
            float h0 = h_s[0][k], h1 = h_s[1][k], h2 = h_s[2][k], h3 = h_s[3][k];
            a00 += w.x * h0;  a01 += w.x * h1;  a02 += w.x * h2;  a03 += w.x * h3;
            a10 += w.y * h0;  a11 += w.y * h1;  a12 += w.y * h2;  a13 += w.y * h3;
        }

        *(float2*)&gates_s[0][gc] = make_float2(a00, a10);
        *(float2*)&gates_s[1][gc] = make_float2(a01, a11);
        *(float2*)&gates_s[2][gc] = make_float2(a02, a12);
        *(float2*)&gates_s[3][gc] = make_float2(a03, a13);
        __syncthreads();

        // pointwise update of 2 hidden-state elements per thread
        {
            float i_ = sigmoidf_(gates_s[r0][j0]);
            float f_ = sigmoidf_(gates_s[r0][HH + j0]);
            float gg = tanhf(gates_s[r0][2 * HH + j0]);
            float o_ = sigmoidf_(gates_s[r0][3 * HH + j0]);
            c0 = f_ * c0 + i_ * gg;
            h_s[r0][j0] = o_ * tanhf(c0);
        }
        {
            float i_ = sigmoidf_(gates_s[r1][j1]);
            float f_ = sigmoidf_(gates_s[r1][HH + j1]);
            float gg = tanhf(gates_s[r1][2 * HH + j1]);
            float o_ = sigmoidf_(gates_s[r1][3 * HH + j1]);
            c1 = f_ * c1 + i_ * gg;
            h_s[r1][j1] = o_ * tanhf(c1);
        }
        __syncthreads();
    }

    g_hfinal[(rb + r0) * HH + j0] = h_s[r0][j0];
    g_hfinal[(rb + r1) * HH + j1] = h_s[r1][j1];
}

// ============================================================
// K3: head — out = relu(h @ W1^T + b1) @ W2^T + b2   (tiny)
// one CTA per batch row, 128 threads
// ============================================================
__global__ __launch_bounds__(128)
void head_kernel(const float* __restrict__ W1, const float* __restrict__ b1,
                 const float* __restrict__ W2, const float* __restrict__ b2,
                 float* __restrict__ out) {
    __shared__ float hrow[HH];
    __shared__ float z[HH];
    const int row = blockIdx.x;
    const int tid = threadIdx.x;

    hrow[tid] = g_hfinal[row * HH + tid];
    __syncthreads();

    float a = b1[tid];
    #pragma unroll 8
    for (int k = 0; k < HH; k++) a += hrow[k] * W1[tid * HH + k];
    z[tid] = fmaxf(a, 0.f);
    __syncthreads();

    if (tid < 3) {
        float a2 = b2[tid];
        #pragma unroll 8
        for (int k = 0; k < HH; k++) a2 += z[k] * W2[tid * HH + k];
        out[row * 3 + tid] = a2;
    }
}

// ============================================================
extern "C" void kernel_launch(void* const* d_in, const int* in_sizes, int n_in,
                              void* d_out, int out_size) {
    const float* x   = (const float*)d_in[0];
    const float* Wih = (const float*)d_in[1];
    const float* Whh = (const float*)d_in[2];
    const float* bih = (const float*)d_in[3];
    const float* bhh = (const float*)d_in[4];
    const float* W1  = (const float*)d_in[5];
    const float* b1  = (const float*)d_in[6];
    const float* W2  = (const float*)d_in[7];
    const float* b2  = (const float*)d_in[8];
    float* out = (float*)d_out;

    prep_kernel<<<256, 256>>>(Wih, Whh, bih, bhh);

    dim3 ggrid(G4 / 128, (BB * TT) / 128);   // (4, 1024)
    gemm_xg_kernel<<<ggrid, 256>>>(x);

    lstm_kernel<<<BB / 4, 256>>>();          // 128 CTAs

    head_kernel<<<BB, HH>>>(W1, b1, W2, b2, out);
}

// round 5
// speedup vs baseline: 1.3463x; 1.3463x over previous
#include <cuda_runtime.h>
#include <math.h>
#include <stdint.h>

#define BB 512      // batch
#define TT 256      // time steps
#define DIN 400     // input dim
#define HH 128      // hidden
#define G4 512      // 4*H

// ---- scratch (device globals: allocation-free per harness rules) ----
__device__ float g_xg[(size_t)BB * TT * G4];   // [B*T, 4H] precomputed input gates (+bias)
__device__ float g_WihT[DIN * G4];             // Wih^T  [K=400][N=512]
__device__ float g_WhhT[HH * G4];              // Whh^T  [K=128][N=512]
__device__ float g_bias[G4];                   // bih + bhh
__device__ float g_hfinal[BB * HH];            // last hidden state

__device__ __forceinline__ uint32_t f2tf32(float f) {
    uint32_t r;
    asm("cvt.rna.tf32.f32 %0, %1;" : "=r"(r) : "f"(f));
    return r;
}

// ============================================================
// K0: prep — transpose weights, combine biases (tiny, one-shot)
// ============================================================
__global__ void prep_kernel(const float* __restrict__ Wih,
                            const float* __restrict__ Whh,
                            const float* __restrict__ bih,
                            const float* __restrict__ bhh) {
    int i = blockIdx.x * blockDim.x + threadIdx.x;
    int stride = gridDim.x * blockDim.x;
    for (int idx = i; idx < DIN * G4; idx += stride) {
        int k = idx / G4, n = idx % G4;
        g_WihT[idx] = Wih[n * DIN + k];
    }
    for (int idx = i; idx < HH * G4; idx += stride) {
        int k = idx / G4, n = idx % G4;
        g_WhhT[idx] = Whh[n * HH + k];
    }
    if (i < G4) g_bias[i] = bih[i] + bhh[i];
}

// ============================================================
// K1: xg = x[M=131072, K=400] @ WihT[K=400, N=512] + bias
// tf32 tensor-core GEMM: mma.sync.aligned.m16n8k8
// BM=128, BN=128, BK=16. 8 warps (2 m x 4 n), warp tile 64x32.
// ============================================================
#define SA 20      // As stride (16 + 4 pad): conflict-free A-frag reads
#define SB 136     // Bs stride (128 + 8 pad): conflict-free B-frag reads

__global__ __launch_bounds__(256)
void gemm_xg_tf32_kernel(const float* __restrict__ x) {
    __shared__ uint32_t As[128 * SA];   // [m][k] as tf32 bits
    __shared__ uint32_t Bs[16 * SB];    // [k][n] as tf32 bits

    const int bn = blockIdx.x;          // 0..3   (N tile)
    const int bm = blockIdx.y;          // 0..1023 (M tile)
    const int tid = threadIdx.x;
    const int w   = tid >> 5;           // warp 0..7
    const int lane = tid & 31;
    const int gid = lane >> 2;          // group id 0..7
    const int tig = lane & 3;           // thread-in-group 0..3
    const int wm = (w & 1) * 64;        // warp m offset (2 warps in m)
    const int wn = (w >> 1) * 32;       // warp n offset (4 warps in n)

    const float* Ag = x + (size_t)bm * 128 * DIN;
    const float* Bg = g_WihT + bn * 128;

    // global->reg load maps (2 float4 each for A and B per thread)
    // A tile: 128 rows x 16 k  = 512 float4
    const int af0 = tid * 2, af1 = tid * 2 + 1;
    const int ar0 = af0 >> 2, ac0 = (af0 & 3) * 4;
    const int ar1 = af1 >> 2, ac1 = (af1 & 3) * 4;
    // B tile: 16 k x 128 n = 512 float4
    const int br0 = af0 >> 5, bc0 = (af0 & 31) * 4;
    const int br1 = af1 >> 5, bc1 = (af1 & 31) * 4;

    float acc[4][4][4];   // [mi][ni][c0..c3]
    #pragma unroll
    for (int mi = 0; mi < 4; mi++)
        #pragma unroll
        for (int ni = 0; ni < 4; ni++)
            #pragma unroll
            for (int c = 0; c < 4; c++) acc[mi][ni][c] = 0.f;

    // prologue: load k-tile 0
    float4 a_v0 = *(const float4*)(Ag + (size_t)ar0 * DIN + ac0);
    float4 a_v1 = *(const float4*)(Ag + (size_t)ar1 * DIN + ac1);
    float4 b_v0 = *(const float4*)(Bg + (size_t)br0 * G4 + bc0);
    float4 b_v1 = *(const float4*)(Bg + (size_t)br1 * G4 + bc1);

    for (int k0 = 0; k0 < DIN; k0 += 16) {   // 25 iterations
        // commit current tile to smem (tf32-rounded)
        {
            uint32_t* p = &As[ar0 * SA + ac0];
            p[0]=f2tf32(a_v0.x); p[1]=f2tf32(a_v0.y); p[2]=f2tf32(a_v0.z); p[3]=f2tf32(a_v0.w);
            p = &As[ar1 * SA + ac1];
            p[0]=f2tf32(a_v1.x); p[1]=f2tf32(a_v1.y); p[2]=f2tf32(a_v1.z); p[3]=f2tf32(a_v1.w);
            p = &Bs[br0 * SB + bc0];
            p[0]=f2tf32(b_v0.x); p[1]=f2tf32(b_v0.y); p[2]=f2tf32(b_v0.z); p[3]=f2tf32(b_v0.w);
            p = &Bs[br1 * SB + bc1];
            p[0]=f2tf32(b_v1.x); p[1]=f2tf32(b_v1.y); p[2]=f2tf32(b_v1.z); p[3]=f2tf32(b_v1.w);
        }
        __syncthreads();

        // prefetch next k-tile while computing
        if (k0 + 16 < DIN) {
            a_v0 = *(const float4*)(Ag + (size_t)ar0 * DIN + k0 + 16 + ac0);
            a_v1 = *(const float4*)(Ag + (size_t)ar1 * DIN + k0 + 16 + ac1);
            b_v0 = *(const float4*)(Bg + (size_t)(k0 + 16 + br0) * G4 + bc0);
            b_v1 = *(const float4*)(Bg + (size_t)(k0 + 16 + br1) * G4 + bc1);
        }

        #pragma unroll
        for (int ks = 0; ks < 16; ks += 8) {
            // A fragments: 4 m-tiles x 4 regs
            uint32_t af[4][4];
            #pragma unroll
            for (int mi = 0; mi < 4; mi++) {
                int r = wm + mi * 16 + gid;
                af[mi][0] = As[(r    ) * SA + ks + tig    ];
                af[mi][1] = As[(r + 8) * SA + ks + tig    ];
                af[mi][2] = As[(r    ) * SA + ks + tig + 4];
                af[mi][3] = As[(r + 8) * SA + ks + tig + 4];
            }
            // B fragments: 4 n-tiles x 2 regs
            uint32_t bf[4][2];
            #pragma unroll
            for (int ni = 0; ni < 4; ni++) {
                int c = wn + ni * 8 + gid;
                bf[ni][0] = Bs[(ks + tig    ) * SB + c];
                bf[ni][1] = Bs[(ks + tig + 4) * SB + c];
            }
            #pragma unroll
            for (int mi = 0; mi < 4; mi++)
                #pragma unroll
                for (int ni = 0; ni < 4; ni++) {
                    asm volatile(
                        "mma.sync.aligned.m16n8k8.row.col.f32.tf32.tf32.f32 "
                        "{%0,%1,%2,%3}, {%4,%5,%6,%7}, {%8,%9}, {%0,%1,%2,%3};"
                        : "+f"(acc[mi][ni][0]), "+f"(acc[mi][ni][1]),
                          "+f"(acc[mi][ni][2]), "+f"(acc[mi][ni][3])
                        : "r"(af[mi][0]), "r"(af[mi][1]), "r"(af[mi][2]), "r"(af[mi][3]),
                          "r"(bf[ni][0]), "r"(bf[ni][1]));
                }
        }
        __syncthreads();
    }

    // epilogue: + bias, write to g_xg
    #pragma unroll
    for (int ni = 0; ni < 4; ni++) {
        int c = wn + ni * 8 + 2 * tig;            // col within 128-tile
        const float bia0 = g_bias[bn * 128 + c];
        const float bia1 = g_bias[bn * 128 + c + 1];
        #pragma unroll
        for (int mi = 0; mi < 4; mi++) {
            int r = wm + mi * 16 + gid;
            float* Cp0 = g_xg + (size_t)(bm * 128 + r    ) * G4 + bn * 128 + c;
            float* Cp1 = g_xg + (size_t)(bm * 128 + r + 8) * G4 + bn * 128 + c;
            *(float2*)Cp0 = make_float2(acc[mi][ni][0] + bia0, acc[mi][ni][1] + bia1);
            *(float2*)Cp1 = make_float2(acc[mi][ni][2] + bia0, acc[mi][ni][3] + bia1);
        }
    }
}

// ============================================================
// K2: LSTM scan. 128 CTAs x 256 threads; CTA owns 4 batch rows,
// iterates all T=256 steps locally. Whh^T streamed from L2
// (float2-coalesced), h in smem, c in registers.
// ============================================================
__device__ __forceinline__ float sigmoidf_(float v) {
    return 1.f / (1.f + __expf(-v));
}

__global__ __launch_bounds__(256)
void lstm_kernel() {
    __shared__ float h_s[4][HH];       // 2 KB
    __shared__ float gates_s[4][G4];   // 8 KB

    const int tid = threadIdx.x;
    const int rb = blockIdx.x * 4;     // first batch row of this CTA

    const int gc = 2 * tid;            // adjacent gate columns {gc, gc+1}
    const int r0 = tid >> 7, j0 = tid & 127;
    const int r1 = (tid + 256) >> 7, j1 = (tid + 256) & 127;

    h_s[r0][j0] = 0.f;
    h_s[r1][j1] = 0.f;
    float c0 = 0.f, c1 = 0.f;
    __syncthreads();

    const float* __restrict__ xg_base = g_xg + (size_t)rb * TT * G4;

    for (int t = 0; t < TT; t++) {
        const float* xgp = xg_base + (size_t)t * G4 + gc;
        float2 x0 = *(const float2*)(xgp + 0 * TT * G4);
        float2 x1 = *(const float2*)(xgp + 1 * TT * G4);
        float2 x2 = *(const float2*)(xgp + 2 * TT * G4);
        float2 x3 = *(const float2*)(xgp + 3 * TT * G4);
        float a00 = x0.x, a01 = x1.x, a02 = x2.x, a03 = x3.x;
        float a10 = x0.y, a11 = x1.y, a12 = x2.y, a13 = x3.y;

        #pragma unroll 4
        for (int k = 0; k < HH; k++) {
            float2 w = *(const float2*)(g_WhhT + k * G4 + gc);
            float h0 = h_s[0][k], h1 = h_s[1][k], h2 = h_s[2][k], h3 = h_s[3][k];
            a00 += w.x * h0;  a01 += w.x * h1;  a02 += w.x * h2;  a03 += w.x * h3;
            a10 += w.y * h0;  a11 += w.y * h1;  a12 += w.y * h2;  a13 += w.y * h3;
        }

        *(float2*)&gates_s[0][gc] = make_float2(a00, a10);
        *(float2*)&gates_s[1][gc] = make_float2(a01, a11);
        *(float2*)&gates_s[2][gc] = make_float2(a02, a12);
        *(float2*)&gates_s[3][gc] = make_float2(a03, a13);
        __syncthreads();

        {
            float i_ = sigmoidf_(gates_s[r0][j0]);
            float f_ = sigmoidf_(gates_s[r0][HH + j0]);
            float gg = tanhf(gates_s[r0][2 * HH + j0]);
            float o_ = sigmoidf_(gates_s[r0][3 * HH + j0]);
            c0 = f_ * c0 + i_ * gg;
            h_s[r0][j0] = o_ * tanhf(c0);
        }
        {
            float i_ = sigmoidf_(gates_s[r1][j1]);
            float f_ = sigmoidf_(gates_s[r1][HH + j1]);
            float gg = tanhf(gates_s[r1][2 * HH + j1]);
            float o_ = sigmoidf_(gates_s[r1][3 * HH + j1]);
            c1 = f_ * c1 + i_ * gg;
            h_s[r1][j1] = o_ * tanhf(c1);
        }
        __syncthreads();
    }

    g_hfinal[(rb + r0) * HH + j0] = h_s[r0][j0];
    g_hfinal[(rb + r1) * HH + j1] = h_s[r1][j1];
}

// ============================================================
// K3: head — out = relu(h @ W1^T + b1) @ W2^T + b2   (tiny)
// ============================================================
__global__ __launch_bounds__(128)
void head_kernel(const float* __restrict__ W1, const float* __restrict__ b1,
                 const float* __restrict__ W2, const float* __restrict__ b2,
                 float* __restrict__ out) {
    __shared__ float hrow[HH];
    __shared__ float z[HH];
    const int row = blockIdx.x;
    const int tid = threadIdx.x;

    hrow[tid] = g_hfinal[row * HH + tid];
    __syncthreads();

    float a = b1[tid];
    #pragma unroll 8
    for (int k = 0; k < HH; k++) a += hrow[k] * W1[tid * HH + k];
    z[tid] = fmaxf(a, 0.f);
    __syncthreads();

    if (tid < 3) {
        float a2 = b2[tid];
        #pragma unroll 8
        for (int k = 0; k < HH; k++) a2 += z[k] * W2[tid * HH + k];
        out[row * 3 + tid] = a2;
    }
}

// ============================================================
extern "C" void kernel_launch(void* const* d_in, const int* in_sizes, int n_in,
                              void* d_out, int out_size) {
    const float* x   = (const float*)d_in[0];
    const float* Wih = (const float*)d_in[1];
    const float* Whh = (const float*)d_in[2];
    const float* bih = (const float*)d_in[3];
    const float* bhh = (const float*)d_in[4];
    const float* W1  = (const float*)d_in[5];
    const float* b1  = (const float*)d_in[6];
    const float* W2  = (const float*)d_in[7];
    const float* b2  = (const float*)d_in[8];
    float* out = (float*)d_out;

    prep_kernel<<<256, 256>>>(Wih, Whh, bih, bhh);

    dim3 ggrid(G4 / 128, (BB * TT) / 128);   // (4, 1024)
    gemm_xg_tf32_kernel<<<ggrid, 256>>>(x);

    lstm_kernel<<<BB / 4, 256>>>();          // 128 CTAs

    head_kernel<<<BB, HH>>>(W1, b1, W2, b2, out);
}

// round 9
// speedup vs baseline: 1.4454x; 1.0736x over previous
#include <cuda_runtime.h>
#include <cuda_fp16.h>
#include <math.h>
#include <stdint.h>

#define BB 512      // batch
#define TT 256      // time steps
#define DIN 400     // input dim
#define KP 416      // DIN padded to 32
#define HH 128      // hidden
#define G4 512      // 4*H

// ---- scratch (device globals: allocation-free per harness rules) ----
__device__ float  g_xg[(size_t)BB * TT * G4];   // [B*T, 4H] input gates (+bias)
__device__ __half g_xh[(size_t)BB * TT * KP];   // x in fp16, K zero-padded (~109MB)
__device__ __half g_WihH[G4 * KP];              // Wih fp16 [N=512][K=416]
__device__ float  g_WhhT[HH * G4];              // Whh^T  [K=128][N=512]
__device__ float  g_bias[G4];                   // bih + bhh
__device__ float  g_hfinal[BB * HH];            // last hidden state

// ============================================================
// K0a: prep — Whh transpose (LSTM), bias combine, Wih -> fp16
// ============================================================
__global__ void prep_kernel(const float* __restrict__ Wih,
                            const float* __restrict__ Whh,
                            const float* __restrict__ bih,
                            const float* __restrict__ bhh) {
    int i = blockIdx.x * blockDim.x + threadIdx.x;
    int stride = gridDim.x * blockDim.x;
    for (int idx = i; idx < HH * G4; idx += stride) {
        int k = idx / G4, n = idx % G4;
        g_WhhT[idx] = Whh[n * HH + k];
    }
    for (int idx = i; idx < G4 * KP; idx += stride) {
        int n = idx / KP, k = idx % KP;
        g_WihH[idx] = (k < DIN) ? __float2half(Wih[n * DIN + k]) : __float2half(0.f);
    }
    if (i < G4) g_bias[i] = bih[i] + bhh[i];
}

// ============================================================
// K0b: x (fp32) -> g_xh (fp16, K padded to 416). One uint4 (8 halves)
// per thread-slot, packed via aligned half2 (no misaligned local cast).
// ============================================================
__global__ void convert_x_kernel(const float* __restrict__ x) {
    const int total = BB * TT * (KP / 8);       // 6,815,744 slots
    for (int id = blockIdx.x * blockDim.x + threadIdx.x; id < total;
         id += gridDim.x * blockDim.x) {
        int row = id / (KP / 8);
        int gk = (id % (KP / 8)) * 8;
        uint4 pack;                              // 16B-aligned local
        __half2* hp = reinterpret_cast<__half2*>(&pack);
        if (gk < DIN) {                          // DIN%8==0: full groups only
            const float* src = x + (size_t)row * DIN + gk;
            float4 v0 = *(const float4*)(src);
            float4 v1 = *(const float4*)(src + 4);
            hp[0] = __floats2half2_rn(v0.x, v0.y);
            hp[1] = __floats2half2_rn(v0.z, v0.w);
            hp[2] = __floats2half2_rn(v1.x, v1.y);
            hp[3] = __floats2half2_rn(v1.z, v1.w);
        } else {
            pack = make_uint4(0u, 0u, 0u, 0u);
        }
        *(uint4*)(g_xh + (size_t)row * KP + gk) = pack;
    }
}

// ============================================================
// K1: xg = x[M=131072, K=416p] @ Wih^T[N=512, K] + bias
// fp16 mma.sync.m16n8k16 (legacy tensor path; tcgen05 not available
// on the harness's sm_100 compile target).
// BM=BN=128, BK=32. 8 warps (2m x 4n), warp tile 64x32.
// ============================================================
#define SAH 20     // smem row stride in uint32 units (= 40 halves, conflict-free)

__global__ __launch_bounds__(256)
void gemm_xg_f16_kernel() {
    __shared__ uint32_t As[128 * SAH];   // [m][k] halves, 40/row
    __shared__ uint32_t Bs[128 * SAH];   // [n][k] halves

    const int bn = blockIdx.x;           // 0..3
    const int bm = blockIdx.y;           // 0..1023
    const int tid = threadIdx.x;
    const int w = tid >> 5, lane = tid & 31;
    const int gid = lane >> 2;           // 0..7
    const int tig = lane & 3;            // 0..3
    const int wm = (w & 1) * 64;
    const int wn = (w >> 1) * 32;

    const __half* Ag = g_xh   + (size_t)bm * 128 * KP;
    const __half* Bg = g_WihH + (size_t)bn * 128 * KP;

    // load map: 128 rows x 32 halves = 512 uint4 slots per operand
    const int s0 = tid, s1 = tid + 256;
    const int ar0 = s0 >> 2, ac0 = (s0 & 3) * 8;   // halves
    const int ar1 = s1 >> 2, ac1 = (s1 & 3) * 8;

    float acc[4][4][4];
    #pragma unroll
    for (int mi = 0; mi < 4; mi++)
        #pragma unroll
        for (int ni = 0; ni < 4; ni++)
            #pragma unroll
            for (int c = 0; c < 4; c++) acc[mi][ni][c] = 0.f;

    // prologue: k-tile 0
    uint4 av0 = *(const uint4*)(Ag + (size_t)ar0 * KP + ac0);
    uint4 av1 = *(const uint4*)(Ag + (size_t)ar1 * KP + ac1);
    uint4 bv0 = *(const uint4*)(Bg + (size_t)ar0 * KP + ac0);
    uint4 bv1 = *(const uint4*)(Bg + (size_t)ar1 * KP + ac1);

    for (int k0 = 0; k0 < KP; k0 += 32) {    // 13 iterations
        *(uint4*)&As[ar0 * SAH + (ac0 >> 1)] = av0;
        *(uint4*)&As[ar1 * SAH + (ac1 >> 1)] = av1;
        *(uint4*)&Bs[ar0 * SAH + (ac0 >> 1)] = bv0;
        *(uint4*)&Bs[ar1 * SAH + (ac1 >> 1)] = bv1;
        __syncthreads();

        if (k0 + 32 < KP) {                  // prefetch next
            av0 = *(const uint4*)(Ag + (size_t)ar0 * KP + k0 + 32 + ac0);
            av1 = *(const uint4*)(Ag + (size_t)ar1 * KP + k0 + 32 + ac1);
            bv0 = *(const uint4*)(Bg + (size_t)ar0 * KP + k0 + 32 + ac0);
            bv1 = *(const uint4*)(Bg + (size_t)ar1 * KP + k0 + 32 + ac1);
        }

        #pragma unroll
        for (int ks = 0; ks < 2; ks++) {     // two k16 steps per tile
            const int kb = ks * 8 + tig;     // uint32 offset within row
            uint32_t af[4][4];
            #pragma unroll
            for (int mi = 0; mi < 4; mi++) {
                int r = wm + mi * 16 + gid;
                af[mi][0] = As[(r    ) * SAH + kb    ];
                af[mi][1] = As[(r + 8) * SAH + kb    ];
                af[mi][2] = As[(r    ) * SAH + kb + 4];
                af[mi][3] = As[(r + 8) * SAH + kb + 4];
            }
            uint32_t bf[4][2];
            #pragma unroll
            for (int ni = 0; ni < 4; ni++) {
                int c = wn + ni * 8 + gid;
                bf[ni][0] = Bs[c * SAH + kb    ];
                bf[ni][1] = Bs[c * SAH + kb + 4];
            }
            #pragma unroll
            for (int mi = 0; mi < 4; mi++)
                #pragma unroll
                for (int ni = 0; ni < 4; ni++) {
                    asm volatile(
                        "mma.sync.aligned.m16n8k16.row.col.f32.f16.f16.f32 "
                        "{%0,%1,%2,%3}, {%4,%5,%6,%7}, {%8,%9}, {%0,%1,%2,%3};"
                        : "+f"(acc[mi][ni][0]), "+f"(acc[mi][ni][1]),
                          "+f"(acc[mi][ni][2]), "+f"(acc[mi][ni][3])
                        : "r"(af[mi][0]), "r"(af[mi][1]), "r"(af[mi][2]), "r"(af[mi][3]),
                          "r"(bf[ni][0]), "r"(bf[ni][1]));
                }
        }
        __syncthreads();
    }

    // epilogue: + bias -> g_xg (fp32)
    #pragma unroll
    for (int ni = 0; ni < 4; ni++) {
        int c = wn + ni * 8 + 2 * tig;
        const float bia0 = g_bias[bn * 128 + c];
        const float bia1 = g_bias[bn * 128 + c + 1];
        #pragma unroll
        for (int mi = 0; mi < 4; mi++) {
            int r = wm + mi * 16 + gid;
            float* Cp0 = g_xg + (size_t)(bm * 128 + r    ) * G4 + bn * 128 + c;
            float* Cp1 = g_xg + (size_t)(bm * 128 + r + 8) * G4 + bn * 128 + c;
            *(float2*)Cp0 = make_float2(acc[mi][ni][0] + bia0, acc[mi][ni][1] + bia1);
            *(float2*)Cp1 = make_float2(acc[mi][ni][2] + bia0, acc[mi][ni][3] + bia1);
        }
    }
}

// ============================================================
// K2: LSTM scan (byte-identical to the 2625us passing kernel)
// ============================================================
__device__ __forceinline__ float sigmoidf_(float v) {
    return 1.f / (1.f + __expf(-v));
}

__global__ __launch_bounds__(256)
void lstm_kernel() {
    __shared__ float h_s[4][HH];
    __shared__ float gates_s[4][G4];

    const int tid = threadIdx.x;
    const int rb = blockIdx.x * 4;

    const int gc = 2 * tid;
    const int r0 = tid >> 7, j0 = tid & 127;
    const int r1 = (tid + 256) >> 7, j1 = (tid + 256) & 127;

    h_s[r0][j0] = 0.f;
    h_s[r1][j1] = 0.f;
    float c0 = 0.f, c1 = 0.f;
    __syncthreads();

    const float* __restrict__ xg_base = g_xg + (size_t)rb * TT * G4;

    for (int t = 0; t < TT; t++) {
        const float* xgp = xg_base + (size_t)t * G4 + gc;
        float2 x0 = *(const float2*)(xgp + 0 * TT * G4);
        float2 x1 = *(const float2*)(xgp + 1 * TT * G4);
        float2 x2 = *(const float2*)(xgp + 2 * TT * G4);
        float2 x3 = *(const float2*)(xgp + 3 * TT * G4);
        float a00 = x0.x, a01 = x1.x, a02 = x2.x, a03 = x3.x;
        float a10 = x0.y, a11 = x1.y, a12 = x2.y, a13 = x3.y;

        #pragma unroll 4
        for (int k = 0; k < HH; k++) {
            float2 w = *(const float2*)(g_WhhT + k * G4 + gc);
            float h0 = h_s[0][k], h1 = h_s[1][k], h2 = h_s[2][k], h3 = h_s[3][k];
            a00 += w.x * h0;  a01 += w.x * h1;  a02 += w.x * h2;  a03 += w.x * h3;
            a10 += w.y * h0;  a11 += w.y * h1;  a12 += w.y * h2;  a13 += w.y * h3;
        }

        *(float2*)&gates_s[0][gc] = make_float2(a00, a10);
        *(float2*)&gates_s[1][gc] = make_float2(a01, a11);
        *(float2*)&gates_s[2][gc] = make_float2(a02, a12);
        *(float2*)&gates_s[3][gc] = make_float2(a03, a13);
        __syncthreads();

        {
            float i_ = sigmoidf_(gates_s[r0][j0]);
            float f_ = sigmoidf_(gates_s[r0][HH + j0]);
            float gg = tanhf(gates_s[r0][2 * HH + j0]);
            float o_ = sigmoidf_(gates_s[r0][3 * HH + j0]);
            c0 = f_ * c0 + i_ * gg;
            h_s[r0][j0] = o_ * tanhf(c0);
        }
        {
            float i_ = sigmoidf_(gates_s[r1][j1]);
            float f_ = sigmoidf_(gates_s[r1][HH + j1]);
            float gg = tanhf(gates_s[r1][2 * HH + j1]);
            float o_ = sigmoidf_(gates_s[r1][3 * HH + j1]);
            c1 = f_ * c1 + i_ * gg;
            h_s[r1][j1] = o_ * tanhf(c1);
        }
        __syncthreads();
    }

    g_hfinal[(rb + r0) * HH + j0] = h_s[r0][j0];
    g_hfinal[(rb + r1) * HH + j1] = h_s[r1][j1];
}

// ============================================================
// K3: head (unchanged)
// ============================================================
__global__ __launch_bounds__(128)
void head_kernel(const float* __restrict__ W1, const float* __restrict__ b1,
                 const float* __restrict__ W2, const float* __restrict__ b2,
                 float* __restrict__ out) {
    __shared__ float hrow[HH];
    __shared__ float z[HH];
    const int row = blockIdx.x;
    const int tid = threadIdx.x;

    hrow[tid] = g_hfinal[row * HH + tid];
    __syncthreads();

    float a = b1[tid];
    #pragma unroll 8
    for (int k = 0; k < HH; k++) a += hrow[k] * W1[tid * HH + k];
    z[tid] = fmaxf(a, 0.f);
    __syncthreads();

    if (tid < 3) {
        float a2 = b2[tid];
        #pragma unroll 8
        for (int k = 0; k < HH; k++) a2 += z[k] * W2[tid * HH + k];
        out[row * 3 + tid] = a2;
    }
}

// ============================================================
extern "C" void kernel_launch(void* const* d_in, const int* in_sizes, int n_in,
                              void* d_out, int out_size) {
    const float* x   = (const float*)d_in[0];
    const float* Wih = (const float*)d_in[1];
    const float* Whh = (const float*)d_in[2];
    const float* bih = (const float*)d_in[3];
    const float* bhh = (const float*)d_in[4];
    const float* W1  = (const float*)d_in[5];
    const float* b1  = (const float*)d_in[6];
    const float* W2  = (const float*)d_in[7];
    const float* b2  = (const float*)d_in[8];
    float* out = (float*)d_out;

    prep_kernel<<<256, 256>>>(Wih, Whh, bih, bhh);
    convert_x_kernel<<<4096, 256>>>(x);

    dim3 ggrid(G4 / 128, (BB * TT) / 128);    // (4, 1024)
    gemm_xg_f16_kernel<<<ggrid, 256>>>();

    lstm_kernel<<<BB / 4, 256>>>();           // 128 CTAs

    head_kernel<<<BB, HH>>>(W1, b1, W2, b2, out);
}